// round 17
// baseline (speedup 1.0000x reference)
#include <cuda_runtime.h>
#include <cuda_bf16.h>
#include <cuda_fp16.h>
#include <cstdint>

// Problem constants
#define BB   512
#define TT   64
#define CC   512
#define HH   512
#define NCLS 96
#define NS   26
#define NBLK 512      // persistent grid (4/SM guaranteed by launch_bounds)

// ---------------- device scratch -------------------------------------------
__device__ __half g_hp16[(size_t)BB * TT * HH];
__device__ __half g_bh16[(size_t)BB * TT * CC];
__device__ __half g_wi16[(size_t)CC * HH];
__device__ __half g_wg16[(size_t)HH * NCLS];
__device__ __half g_wh16[(size_t)HH * HH];
__device__ __half g_lr16[(size_t)HH * 4 * HH];
__device__ __half g_lk16[(size_t)(CC + NCLS) * 4 * HH];
__device__ float  g_lbP [(size_t)4 * HH];
__device__ float  g_q   [(size_t)BB * HH];
__device__ float  g_zh  [(size_t)BB * 4 * HH];
__device__ __half g_h16A[(size_t)BB * HH];
__device__ __half g_h16B[(size_t)BB * HH];
__device__ __half g_ctx16[(size_t)BB * CC];
__device__ __half g_hs16[(size_t)BB * NS * HH];
__device__ float  g_c  [(size_t)BB * HH];
__device__ unsigned g_bar_count;
__device__ unsigned g_bar_sense;

// ---------------- helpers ----------------------------------------------------
__device__ __forceinline__ float sigm(float x) { return 1.f / (1.f + __expf(-x)); }
__device__ __forceinline__ float tanha(float x) {
    float y;
    asm("tanh.approx.f32 %0, %1;" : "=f"(y) : "f"(x));
    return y;
}
__device__ __forceinline__ void mma16816(float* d, const uint32_t* a, const uint32_t* b) {
    asm volatile(
        "mma.sync.aligned.m16n8k16.row.col.f32.f16.f16.f32 "
        "{%0,%1,%2,%3}, {%4,%5,%6,%7}, {%8,%9}, {%0,%1,%2,%3};"
        : "+f"(d[0]), "+f"(d[1]), "+f"(d[2]), "+f"(d[3])
        : "r"(a[0]), "r"(a[1]), "r"(a[2]), "r"(a[3]),
          "r"(b[0]), "r"(b[1]));
}
__device__ __forceinline__ void ldsm_x4(uint32_t* r, uint32_t addr) {
    asm volatile("ldmatrix.sync.aligned.m8n8.x4.shared.b16 {%0,%1,%2,%3}, [%4];"
        : "=r"(r[0]), "=r"(r[1]), "=r"(r[2]), "=r"(r[3]) : "r"(addr));
}
__device__ __forceinline__ void ldsm_x4_t(uint32_t* r, uint32_t addr) {
    asm volatile("ldmatrix.sync.aligned.m8n8.x4.trans.shared.b16 {%0,%1,%2,%3}, [%4];"
        : "=r"(r[0]), "=r"(r[1]), "=r"(r[2]), "=r"(r[3]) : "r"(addr));
}

// grid barrier: sense-reversing, release/acquire via threadfence
__device__ __forceinline__ void gbar(unsigned& local_sense) {
    __syncthreads();
    if (threadIdx.x == 0) {
        const unsigned target = local_sense + 1;
        __threadfence();
        unsigned old = atomicAdd(&g_bar_count, 1u);
        if (old == NBLK - 1) {
            g_bar_count = 0;
            __threadfence();
            atomicExch(&g_bar_sense, target);
        } else {
            while (atomicAdd(&g_bar_sense, 0u) < target) __nanosleep(64);
        }
        __threadfence();
        local_sense = target;
    }
    __syncthreads();
}

// ---------------- fp16 cp.async 3-stage GEMM core ----------------------------
// Block tile 64 x (NT*16), BK=32 halves, 128 threads, 4 warps, warp 32 x (NT*8).
// MODE 0: fp32 C. MODE 1: z=ctx@lk + zh + LSTM gates. MODE 2: fp16 C.
template<int MODE, int NT>
__device__ __forceinline__
void gemm_core(int bx, int by,
               const __half* __restrict__ A1, const __half* __restrict__ B1,
               const float* __restrict__ bias, float* __restrict__ C,
               int M, int N, int K, int lda, int ldb, int ldc,
               const __half* __restrict__ lk16, const float* __restrict__ lbP,
               const int* __restrict__ text, int step,
               const float* __restrict__ zhp)
{
    constexpr int BN = NT * 16;
    constexpr int PA = 40;
    constexpr int PB = BN + 8;
    constexpr int A_H = 64 * PA;
    constexpr int B_H = 32 * PB;
    constexpr int STAGE_BYTES = (A_H + B_H) * 2;
    constexpr int BCH = BN / 8;

    extern __shared__ __half SMh[];
    const int tid = threadIdx.x;
    const int wid = tid >> 5, lane = tid & 31;
    const int warpM = wid >> 1, warpN = wid & 1;
    const int g = lane >> 2, t = lane & 3;
    const int m0 = by * 64, n0 = bx * BN;
    const int nk = K / 32;
    const uint32_t sbase = (uint32_t)__cvta_generic_to_shared(SMh);

    const int lr8 = lane & 7;
    const int selR = (lane >> 3) & 1;
    const int selC = (lane >> 4) & 1;

    float acc[2][NT][4];
#pragma unroll
    for (int i = 0; i < 2; ++i)
#pragma unroll
        for (int j = 0; j < NT; ++j)
#pragma unroll
            for (int k = 0; k < 4; ++k) acc[i][j][k] = 0.f;

    auto issue = [&](int kt) {
        if (kt < nk) {
            const int k0 = kt * 32;
            const uint32_t ab = sbase + (uint32_t)(kt % 3) * STAGE_BYTES;
            const uint32_t bb = ab + A_H * 2;
#pragma unroll
            for (int i = 0; i < 2; ++i) {
                const int lin = tid + 128 * i;
                const int row = lin >> 2, q = lin & 3;
                const uint32_t d = ab + (uint32_t)(row * PA + q * 8) * 2u;
                const __half* s = A1 + (size_t)(m0 + row) * lda + k0 + q * 8;
                asm volatile("cp.async.cg.shared.global [%0], [%1], 16;"
                             :: "r"(d), "l"(s));
            }
#pragma unroll
            for (int i = 0; i < (32 * BCH) / 128; ++i) {
                const int lin = tid + 128 * i;
                const int kk = lin / BCH, q = lin % BCH;
                const uint32_t d = bb + (uint32_t)(kk * PB + q * 8) * 2u;
                const __half* s = B1 + (size_t)(k0 + kk) * ldb + n0 + q * 8;
                asm volatile("cp.async.cg.shared.global [%0], [%1], 16;"
                             :: "r"(d), "l"(s));
            }
        }
        asm volatile("cp.async.commit_group;" ::: "memory");
    };

    issue(0);
    issue(1);

    for (int kt = 0; kt < nk; ++kt) {
        asm volatile("cp.async.wait_group 1;" ::: "memory");
        __syncthreads();
        issue(kt + 2);

        const uint32_t ab = sbase + (uint32_t)(kt % 3) * STAGE_BYTES;
        const uint32_t bb = ab + A_H * 2;

        uint32_t fa[2][2][4], fb[2][NT][2];
        auto ldfrag = [&](int kb16, int slot) {
            const int kh = kb16 * 16;
#pragma unroll
            for (int mt = 0; mt < 2; ++mt) {
                const int row = warpM * 32 + mt * 16 + lr8 + selR * 8;
                const int col = kh + selC * 8;
                ldsm_x4(fa[slot][mt], ab + (uint32_t)(row * PA + col) * 2u);
            }
#pragma unroll
            for (int np = 0; np < NT / 2; ++np) {
                const int bk = kh + lr8 + selR * 8;
                const int bn = warpN * (NT * 8) + np * 16 + selC * 8;
                uint32_t q4[4];
                ldsm_x4_t(q4, bb + (uint32_t)(bk * PB + bn) * 2u);
                fb[slot][2 * np][0] = q4[0]; fb[slot][2 * np][1] = q4[1];
                fb[slot][2 * np + 1][0] = q4[2]; fb[slot][2 * np + 1][1] = q4[3];
            }
        };

        ldfrag(0, 0);
        ldfrag(1, 1);
#pragma unroll
        for (int s = 0; s < 2; ++s)
#pragma unroll
            for (int mt = 0; mt < 2; ++mt)
#pragma unroll
                for (int nt = 0; nt < NT; ++nt)
                    mma16816(acc[mt][nt], fa[s][mt], fb[s][nt]);
    }

    if (MODE == 0) {
#pragma unroll
        for (int mt = 0; mt < 2; ++mt) {
#pragma unroll
            for (int nt = 0; nt < NT; ++nt) {
                const int col = n0 + warpN * (NT * 8) + nt * 8 + 2 * t;
                const int row = m0 + warpM * 32 + mt * 16 + g;
                float b0 = bias ? bias[col] : 0.f;
                float b1 = bias ? bias[col + 1] : 0.f;
                *(float2*)(C + (size_t)row * ldc + col) =
                    make_float2(acc[mt][nt][0] + b0, acc[mt][nt][1] + b1);
                *(float2*)(C + (size_t)(row + 8) * ldc + col) =
                    make_float2(acc[mt][nt][2] + b0, acc[mt][nt][3] + b1);
            }
        }
    } else if (MODE == 2) {
        __half* C16 = (__half*)C;
#pragma unroll
        for (int mt = 0; mt < 2; ++mt) {
#pragma unroll
            for (int nt = 0; nt < NT; ++nt) {
                const int col = n0 + warpN * (NT * 8) + nt * 8 + 2 * t;
                const int row = m0 + warpM * 32 + mt * 16 + g;
                *(__half2*)(C16 + (size_t)row * ldc + col) =
                    __floats2half2_rn(acc[mt][nt][0], acc[mt][nt][1]);
                *(__half2*)(C16 + (size_t)(row + 8) * ldc + col) =
                    __floats2half2_rn(acc[mt][nt][2], acc[mt][nt][3]);
            }
        }
    } else {
        __syncthreads();
        float* zs = (float*)SMh;
        constexpr int ZP = BN + 2;
#pragma unroll
        for (int mt = 0; mt < 2; ++mt) {
#pragma unroll
            for (int nt = 0; nt < NT; ++nt) {
                const int c0 = warpN * (NT * 8) + nt * 8 + 2 * t;
                const int r0 = warpM * 32 + mt * 16 + g;
                zs[r0 * ZP + c0]           = acc[mt][nt][0];
                zs[r0 * ZP + c0 + 1]       = acc[mt][nt][1];
                zs[(r0 + 8) * ZP + c0]     = acc[mt][nt][2];
                zs[(r0 + 8) * ZP + c0 + 1] = acc[mt][nt][3];
            }
        }
        __syncthreads();
        __half* hout = (__half*)C;
        const int j0 = n0 >> 2;
        constexpr int NJ = BN / 4;
#pragma unroll
        for (int p = tid; p < 64 * NJ; p += 128) {
            const int r = p & 63, jj = p >> 6;
            const int b = m0 + r, j = j0 + jj;
            const int ch = text[b * NS + step];
            const float* zrow = zs + r * ZP + jj * 4;
            const __half2* ohp =
                (const __half2*)(lk16 + (size_t)(CC + ch) * (4 * HH) + 4 * j);
            float2 o01 = __half22float2(ohp[0]);
            float2 o23 = __half22float2(ohp[1]);
            float4 bb4 = *(const float4*)(lbP + 4 * j);
            float4 zh4 = *(const float4*)(zhp + (size_t)b * (4 * HH) + 4 * j);
            float zi = zrow[0] + zh4.x + o01.x + bb4.x;
            float zf = zrow[1] + zh4.y + o01.y + bb4.y;
            float zg = zrow[2] + zh4.z + o23.x + bb4.z;
            float zo = zrow[3] + zh4.w + o23.y + bb4.w;
            const int ci = b * HH + j;
            float cn = sigm(zf) * g_c[ci] + sigm(zi) * tanhf(zg);
            float hn = sigm(zo) * tanhf(cn);
            __half hh = __float2half_rn(hn);
            g_c[ci] = cn;
            hout[ci] = hh;
            g_hs16[((size_t)b * NS + step) * HH + j] = hh;
        }
        __syncthreads();   // protect smem reuse before next phase
    }
}

// generic GEMM kernel wrapper (Hproj / final projection)
template<int MODE, int NT>
__global__ __launch_bounds__(128)
void gemm_h(const __half* __restrict__ A1, const __half* __restrict__ B1,
            const float* __restrict__ bias, float* __restrict__ C,
            int M, int N, int K, int lda, int ldb, int ldc)
{
    gemm_core<MODE, NT>(blockIdx.x, blockIdx.y, A1, B1, bias, C,
                        M, N, K, lda, ldb, ldc,
                        nullptr, nullptr, nullptr, 0, nullptr);
}

// ---------------- attention body (128 threads, tanh.approx) ------------------
__device__ __forceinline__
void attn_body(int b,
               const float* __restrict__ q, const float* __restrict__ bh,
               const __half* __restrict__ hp16, const __half* __restrict__ bh16,
               const float* __restrict__ Ws, __half* __restrict__ ctx16)
{
    extern __shared__ __half SMh[];
    float* qs = (float*)SMh;
    float* ws = qs + HH;
    float* e  = ws + HH;

    const int tid = threadIdx.x;
    __syncthreads();                    // smem reuse guard
    for (int i = tid; i < HH; i += 128) {
        qs[i] = q[(size_t)b * HH + i] + bh[i];
        ws[i] = Ws[i];
    }
    __syncthreads();

    const int warp = tid >> 5, lane = tid & 31;
    for (int t = warp; t < TT; t += 4) {
        const __half2* __restrict__ hp =
            (const __half2*)(hp16 + ((size_t)b * TT + t) * HH);
        float p = 0.f;
#pragma unroll
        for (int j = 0; j < 8; ++j) {
            const int idx = lane + 32 * j;
            float2 f = __half22float2(hp[idx]);
            float2 qv = *(const float2*)&qs[2 * idx];
            float2 wv = *(const float2*)&ws[2 * idx];
            p += tanha(f.x + qv.x) * wv.x + tanha(f.y + qv.y) * wv.y;
        }
#pragma unroll
        for (int o = 16; o; o >>= 1) p += __shfl_xor_sync(0xffffffffu, p, o);
        if (lane == 0) e[t] = p;
    }
    __syncthreads();

    if (warp == 0) {
        float v0 = e[lane], v1 = e[lane + 32];
        float m = fmaxf(v0, v1);
#pragma unroll
        for (int o = 16; o; o >>= 1) m = fmaxf(m, __shfl_xor_sync(0xffffffffu, m, o));
        float x0 = __expf(v0 - m), x1 = __expf(v1 - m);
        float s = x0 + x1;
#pragma unroll
        for (int o = 16; o; o >>= 1) s += __shfl_xor_sync(0xffffffffu, s, o);
        float inv = 1.f / s;
        e[lane] = x0 * inv;
        e[lane + 32] = x1 * inv;
    }
    __syncthreads();

    {
        const __half2* __restrict__ bp =
            (const __half2*)(bh16 + (size_t)b * TT * CC);
#pragma unroll
        for (int cc = tid; cc < CC / 2; cc += 128) {
            float2 acc = make_float2(0.f, 0.f);
#pragma unroll 8
            for (int t = 0; t < TT; ++t) {
                float2 f = __half22float2(bp[t * (CC / 2) + cc]);
                float a = e[t];
                acc.x = fmaf(a, f.x, acc.x);
                acc.y = fmaf(a, f.y, acc.y);
            }
            ((__half2*)ctx16)[(size_t)b * (CC / 2) + cc] =
                __floats2half2_rn(acc.x, acc.y);
        }
    }
    __syncthreads();
}

// ---------------- persistent decode loop -------------------------------------
__global__ __launch_bounds__(128, 4)
void decode_loop(const __half* __restrict__ wh16, const __half* __restrict__ lr16,
                 const __half* __restrict__ lk16, const float* __restrict__ lbP,
                 const float* __restrict__ bh, const float* __restrict__ Ws,
                 const __half* __restrict__ hp16, const __half* __restrict__ bh16,
                 const int* __restrict__ text,
                 float* __restrict__ q, float* __restrict__ zh,
                 __half* __restrict__ ctx16,
                 __half* __restrict__ hA, __half* __restrict__ hB)
{
    unsigned local_sense = 0;
    const int blk = blockIdx.x;

    for (int s = 0; s < NS; ++s) {
        const __half* hin = (s & 1) ? hB : hA;
        __half* hout = (s & 1) ? hA : hB;

        // phase 1: q = h @ wh16  (128 tiles: 16 nx x 8 my, BN=32)
        for (int w = blk; w < 128; w += NBLK)
            gemm_core<0, 2>(w & 15, w >> 4, hin, wh16, nullptr, q,
                            BB, HH, HH, HH, HH, HH,
                            nullptr, nullptr, nullptr, 0, nullptr);
        gbar(local_sense);

        // phase 2: attn rows (0..511) + zh tiles (512..767: 32 nx x 8 my, BN=64)
        for (int w = blk; w < 768; w += NBLK) {
            if (w < 512) {
                attn_body(w, q, bh, hp16, bh16, Ws, ctx16);
            } else {
                const int tile = w - 512;
                gemm_core<0, 4>(tile & 31, tile >> 5, hin, lr16, nullptr, zh,
                                BB, 4 * HH, HH, HH, 4 * HH, 4 * HH,
                                nullptr, nullptr, nullptr, 0, nullptr);
            }
        }
        gbar(local_sense);

        // phase 3: fused z = ctx @ lk16 + zh + gates (256 tiles, BN=64)
        for (int w = blk; w < 256; w += NBLK)
            gemm_core<1, 4>(w & 31, w >> 5, ctx16, lk16, nullptr, (float*)hout,
                            BB, 4 * HH, CC, CC, 4 * HH, 4 * HH,
                            lk16, lbP, text, s, zh);
        gbar(local_sense);
    }
}

// ---------------- prep kernels ------------------------------------------------
__global__ __launch_bounds__(256)
void permute_gates_h(const float* __restrict__ in, __half* __restrict__ out, int total)
{
    int idx = blockIdx.x * 256 + threadIdx.x;
    if (idx >= total) return;
    int row = idx >> 11, oc = idx & 2047;
    int j = oc >> 2, gate = oc & 3;
    out[idx] = __float2half_rn(in[(size_t)row * 2048 + gate * HH + j]);
}
__global__ __launch_bounds__(256)
void permute_bias(const float* __restrict__ in, float* __restrict__ out)
{
    int idx = blockIdx.x * 256 + threadIdx.x;
    if (idx >= 4 * HH) return;
    int j = idx >> 2, gate = idx & 3;
    out[idx] = in[gate * HH + j];
}
__global__ __launch_bounds__(256)
void half_copy(const float* __restrict__ in, __half* __restrict__ out, int n4)
{
    int i = blockIdx.x * 256 + threadIdx.x;
    if (i >= n4) return;
    float4 v = ((const float4*)in)[i];
    ((__half2*)out)[2 * i]     = __floats2half2_rn(v.x, v.y);
    ((__half2*)out)[2 * i + 1] = __floats2half2_rn(v.z, v.w);
}

// ---------------- launch -----------------------------------------------------
extern "C" void kernel_launch(void* const* d_in, const int* in_sizes, int n_in,
                              void* d_out, int out_size)
{
    int off = 0;
    if (n_in >= 3 && in_sizes[2] == 1) off = 1;
    const float* batch_H = (const float*)d_in[0];
    const int*   text    = (const int*)  d_in[1];
    const float* Wi      = (const float*)d_in[2 + off];
    const float* Wh      = (const float*)d_in[3 + off];
    const float* bh      = (const float*)d_in[4 + off];
    const float* Ws      = (const float*)d_in[5 + off];
    const float* lk      = (const float*)d_in[6 + off];
    const float* lr      = (const float*)d_in[7 + off];
    const float* lb      = (const float*)d_in[8 + off];
    const float* Wgen    = (const float*)d_in[9 + off];
    const float* bgen    = (const float*)d_in[10 + off];

    __half *hp16, *bh16, *wi16, *wg16, *wh16, *lr16, *lk16, *hA, *hB, *ctx16, *hs16;
    float *lbP, *q, *zh, *c;
    unsigned *barc, *bars;
    cudaGetSymbolAddress((void**)&hp16, g_hp16);
    cudaGetSymbolAddress((void**)&bh16, g_bh16);
    cudaGetSymbolAddress((void**)&wi16, g_wi16);
    cudaGetSymbolAddress((void**)&wg16, g_wg16);
    cudaGetSymbolAddress((void**)&wh16, g_wh16);
    cudaGetSymbolAddress((void**)&lr16, g_lr16);
    cudaGetSymbolAddress((void**)&lk16, g_lk16);
    cudaGetSymbolAddress((void**)&lbP,  g_lbP);
    cudaGetSymbolAddress((void**)&q,    g_q);
    cudaGetSymbolAddress((void**)&zh,   g_zh);
    cudaGetSymbolAddress((void**)&hA,   g_h16A);
    cudaGetSymbolAddress((void**)&hB,   g_h16B);
    cudaGetSymbolAddress((void**)&ctx16,g_ctx16);
    cudaGetSymbolAddress((void**)&hs16, g_hs16);
    cudaGetSymbolAddress((void**)&c,    g_c);
    cudaGetSymbolAddress((void**)&barc, g_bar_count);
    cudaGetSymbolAddress((void**)&bars, g_bar_sense);

    static bool attr_done = false;
    if (!attr_done) {
        cudaFuncSetAttribute(gemm_h<0,2>, cudaFuncAttributeMaxDynamicSharedMemorySize, 23040);
        cudaFuncSetAttribute(gemm_h<2,8>, cudaFuncAttributeMaxDynamicSharedMemorySize, 41472);
        cudaFuncSetAttribute(decode_loop, cudaFuncAttributeMaxDynamicSharedMemorySize, 29184);
        attr_done = true;
    }

    cudaMemsetAsync(hA, 0, (size_t)BB * HH * sizeof(__half));
    cudaMemsetAsync(c,  0, (size_t)BB * HH * sizeof(float));
    cudaMemsetAsync(barc, 0, sizeof(unsigned));
    cudaMemsetAsync(bars, 0, sizeof(unsigned));

    // prep
    half_copy<<<(BB * TT * CC / 4 + 255) / 256, 256>>>(batch_H, bh16, BB * TT * CC / 4);
    half_copy<<<(CC * HH / 4 + 255) / 256, 256>>>(Wi, wi16, CC * HH / 4);
    half_copy<<<(HH * HH / 4 + 255) / 256, 256>>>(Wh, wh16, HH * HH / 4);
    half_copy<<<(HH * NCLS / 4 + 255) / 256, 256>>>(Wgen, wg16, HH * NCLS / 4);
    permute_gates_h<<<((CC + NCLS) * 4 * HH + 255) / 256, 256>>>(lk, lk16, (CC + NCLS) * 4 * HH);
    permute_gates_h<<<(HH * 4 * HH + 255) / 256, 256>>>(lr, lr16, HH * 4 * HH);
    permute_bias<<<(4 * HH + 255) / 256, 256>>>(lb, lbP);

    // Hproj(fp16) = bh16 [B*T, C] @ wi16 [C, H]   (BN=128, grid 2048)
    gemm_h<2,8><<<dim3(HH / 128, (BB * TT) / 64), 128, 41472>>>(
        bh16, wi16, nullptr, (float*)hp16,
        BB * TT, HH, CC, CC, HH, HH);

    // persistent 26-step decode loop (one launch, grid barriers inside)
    decode_loop<<<NBLK, 128, 29184>>>(
        wh16, lr16, lk16, lbP, bh, Ws, hp16, bh16, text,
        q, zh, ctx16, hA, hB);

    // probs = hs16 [B*NS, H] @ wg16 [H, NC] + bgen  (BN=32, grid 624)
    gemm_h<0,2><<<dim3(NCLS / 32, (BB * NS) / 64), 128, 23040>>>(
        hs16, wg16, bgen, (float*)d_out,
        BB * NS, NCLS, HH, HH, NCLS, NCLS);
}